// round 7
// baseline (speedup 1.0000x reference)
#include <cuda_runtime.h>
#include <cuda_bf16.h>
#include <cstdint>

// ---------------------------------------------------------------------------
// Problem constants
// ---------------------------------------------------------------------------
#define N_ROWS 16384
#define K_ROWS 2048
#define D_DIM  1024

#define BM 128
#define BN 128
#define BK 64                   // bf16 -> 128 B per smem row (SW128 atom)
#define NKT (D_DIM / BK)        // 16 k-tiles
#define STAGES 3
#define A_STAGE_BYTES (BM * 128)                      // 16 KB
#define B_STAGE_BYTES (BN * 128)                      // 16 KB
#define STAGE_BYTES (A_STAGE_BYTES + B_STAGE_BYTES)   // 32 KB
#define SM_ALLOC (STAGES * STAGE_BYTES)               // 96 KB -> 2 CTAs/SM

#define NTHREADS 288            // 8 consumer warps + 1 producer warp

// bf16 mirrors + squared norms (device globals: allocation-free scratch)
// feat mirror is pre-scaled by 2 (exact power of two) so epilogue = fs+cs-cross
__device__ __nv_bfloat16 g_feat_bf[(size_t)N_ROWS * D_DIM];   // 32 MB
__device__ __nv_bfloat16 g_cent_bf[(size_t)K_ROWS * D_DIM];   //  4 MB
__device__ float g_feat_sq[N_ROWS];
__device__ float g_cent_sq[K_ROWS];

// ---------------------------------------------------------------------------
// helpers
// ---------------------------------------------------------------------------
__device__ __forceinline__ void cp_async16(uint32_t saddr, const void* gaddr) {
    asm volatile("cp.async.cg.shared.global [%0], [%1], 16;" :: "r"(saddr), "l"(gaddr));
}

__device__ __forceinline__ void ldsm_x4(uint32_t* r, uint32_t addr) {
    asm volatile("ldmatrix.sync.aligned.m8n8.x4.shared.b16 {%0,%1,%2,%3}, [%4];"
                 : "=r"(r[0]), "=r"(r[1]), "=r"(r[2]), "=r"(r[3]) : "r"(addr));
}

__device__ __forceinline__ void mma16816(float* c, const uint32_t* a,
                                         uint32_t b0, uint32_t b1) {
    asm volatile(
        "mma.sync.aligned.m16n8k16.row.col.f32.bf16.bf16.f32 "
        "{%0,%1,%2,%3}, {%4,%5,%6,%7}, {%8,%9}, {%0,%1,%2,%3};\n"
        : "+f"(c[0]), "+f"(c[1]), "+f"(c[2]), "+f"(c[3])
        : "r"(a[0]), "r"(a[1]), "r"(a[2]), "r"(a[3]), "r"(b0), "r"(b1));
}

// acquire-parity wait (spin). try_wait fast path + poll loop.
__device__ __forceinline__ void mbar_wait(uint32_t mbar, uint32_t parity) {
    uint32_t done;
    asm volatile(
        "{\n\t.reg .pred p;\n\t"
        "mbarrier.try_wait.parity.acquire.cta.shared::cta.b64 p, [%1], %2;\n\t"
        "selp.b32 %0, 1, 0, p;\n\t}"
        : "=r"(done) : "r"(mbar), "r"(parity) : "memory");
    if (!done) {
        asm volatile(
            "{\n\t.reg .pred P1;\n\t"
            "WL_%=:\n\t"
            "mbarrier.try_wait.parity.acquire.cta.shared::cta.b64 P1, [%0], %1, 0x989680;\n\t"
            "@P1 bra.uni WD_%=;\n\t"
            "bra.uni WL_%=;\n\t"
            "WD_%=:\n\t}"
            :: "r"(mbar), "r"(parity) : "memory");
    }
}

// ---------------------------------------------------------------------------
// fp32 -> bf16 conversion fused with row squared-norms. One warp per row.
// feat rows are scaled by 2.0f (exact) before bf16 rounding.
// ---------------------------------------------------------------------------
__global__ void convert_norms_kernel(const float* __restrict__ feat,
                                     const float* __restrict__ cent) {
    int grow = blockIdx.x * 8 + (threadIdx.x >> 5);
    int lane = threadIdx.x & 31;
    const float* src;
    __nv_bfloat16* dst;
    float* sq;
    int row;
    float scale;
    if (grow < N_ROWS) { src = feat; dst = g_feat_bf; sq = g_feat_sq; row = grow; scale = 2.f; }
    else               { src = cent; dst = g_cent_bf; sq = g_cent_sq; row = grow - N_ROWS; scale = 1.f; }

    const float4* p = reinterpret_cast<const float4*>(src) + (size_t)row * (D_DIM / 4);
    uint2* d = reinterpret_cast<uint2*>(dst + (size_t)row * D_DIM);
    float s = 0.f;
#pragma unroll
    for (int i = lane; i < D_DIM / 4; i += 32) {
        float4 v = p[i];
        s += v.x * v.x + v.y * v.y + v.z * v.z + v.w * v.w;
        __nv_bfloat162 lo = __floats2bfloat162_rn(v.x * scale, v.y * scale);
        __nv_bfloat162 hi = __floats2bfloat162_rn(v.z * scale, v.w * scale);
        uint2 u;
        u.x = *reinterpret_cast<uint32_t*>(&lo);
        u.y = *reinterpret_cast<uint32_t*>(&hi);
        d[i] = u;
    }
#pragma unroll
    for (int o = 16; o > 0; o >>= 1) s += __shfl_xor_sync(0xffffffffu, s, o);
    if (lane == 0) sq[row] = s;
}

// ---------------------------------------------------------------------------
// Warp-specialized distance GEMM.
//   producer (warp 8): cp.async fills stages; async arrival via
//                      cp.async.mbarrier.arrive.NOINC (full count = 32).
//   consumers (warps 0-7): wait full -> 24 LDSM + 64 HMMA -> arrive empty (count 8).
// No __syncthreads in the mainloop. 2 CTAs/SM.
// out = feat_sq[m] + cent_sq[n] - (2*feat).cent
// ---------------------------------------------------------------------------
__global__ void __launch_bounds__(NTHREADS, 2)
dist_gemm_kernel(float* __restrict__ out) {
    extern __shared__ __align__(1024) char smem[];
    __shared__ __align__(8) uint64_t mbars[2 * STAGES];   // [full0..2, empty0..2]
    const uint32_t smem_u = (uint32_t)__cvta_generic_to_shared(smem);
    const uint32_t mb_u   = (uint32_t)__cvta_generic_to_shared(mbars);

    const int tid  = threadIdx.x;
    const int warp = tid >> 5;
    const int lane = tid & 31;

    const int m0 = blockIdx.y * BM;
    const int n0 = blockIdx.x * BN;

    if (tid == 0) {
#pragma unroll
        for (int s = 0; s < STAGES; s++) {
            asm volatile("mbarrier.init.shared.b64 [%0], 32;"
                         :: "r"(mb_u + s * 8) : "memory");                 // full
            asm volatile("mbarrier.init.shared.b64 [%0], 8;"
                         :: "r"(mb_u + (STAGES + s) * 8) : "memory");      // empty
        }
    }
    __syncthreads();

    if (warp == 8) {
        // ----------------- producer -----------------
        const int r0 = lane * 4;                       // 4 rows per lane
        const __nv_bfloat16* ag0 = g_feat_bf + (size_t)(m0 + r0) * D_DIM;
        const __nv_bfloat16* bg0 = g_cent_bf + (size_t)(n0 + r0) * D_DIM;
        // smem offsets for the 4 rows x 8 chunks (swizzled), loop-invariant
        uint32_t soff[4][8];
#pragma unroll
        for (int r = 0; r < 4; r++) {
            uint32_t rx = ((r0 + r) & 7) << 4;
#pragma unroll
            for (int q = 0; q < 8; q++)
                soff[r][q] = (r0 + r) * 128 + ((q * 16) ^ rx);
        }

        int s = 0, phase = 1;
        for (int kt = 0; kt < NKT; kt++) {
            mbar_wait(mb_u + (STAGES + s) * 8, phase);  // wait stage empty
            const uint32_t ab = smem_u + s * STAGE_BYTES;
            const uint32_t bb = ab + A_STAGE_BYTES;
            const __nv_bfloat16* ag = ag0 + kt * BK;
            const __nv_bfloat16* bg = bg0 + kt * BK;
#pragma unroll
            for (int r = 0; r < 4; r++)
#pragma unroll
                for (int q = 0; q < 8; q++)
                    cp_async16(ab + soff[r][q], ag + (size_t)r * D_DIM + q * 8);
#pragma unroll
            for (int r = 0; r < 4; r++)
#pragma unroll
                for (int q = 0; q < 8; q++)
                    cp_async16(bb + soff[r][q], bg + (size_t)r * D_DIM + q * 8);
            // NOINC: consumes one of the 32 init arrivals when this thread's
            // outstanding cp.asyncs land (the non-noinc form is self-balancing
            // and would never complete the phase -> R5 deadlock).
            asm volatile("cp.async.mbarrier.arrive.noinc.shared::cta.b64 [%0];"
                         :: "r"(mb_u + s * 8) : "memory");
            if (++s == STAGES) { s = 0; phase ^= 1; }
        }
        return;   // producer done; no epilogue work
    }

    // ----------------- consumers (warps 0..7) -----------------
    const int wm = (warp >> 2) * 64;   // warp M offset: 0 / 64
    const int wn = (warp & 3) * 32;    // warp N offset: 0 / 32 / 64 / 96

    const int fr_lo = lane & 15;                 // row within 16-row fragment
    const uint32_t fr_hi16 = (lane >> 4) * 16;   // k-byte offset 0/16

    uint32_t a_rowb[4], a_rx[4], b_rowb[2], b_rx[2];
#pragma unroll
    for (int im = 0; im < 4; im++) {
        int r = wm + im * 16 + fr_lo;
        a_rowb[im] = r * 128;
        a_rx[im]   = (r & 7) << 4;
    }
#pragma unroll
    for (int ib = 0; ib < 2; ib++) {
        int r = wn + ib * 16 + fr_lo;
        b_rowb[ib] = r * 128;
        b_rx[ib]   = (r & 7) << 4;
    }

    float acc[4][4][4] = {};   // [im][in][creg]

    int s = 0, phase = 0;
    for (int kt = 0; kt < NKT; kt++) {
        mbar_wait(mb_u + s * 8, phase);            // wait stage full
        const uint32_t abase = smem_u + s * STAGE_BYTES;
        const uint32_t bbase = abase + A_STAGE_BYTES;

#pragma unroll
        for (int ks = 0; ks < 4; ks++) {
            const uint32_t kb = ks * 32 + fr_hi16;
            uint32_t a[4][4], bq[2][4];
#pragma unroll
            for (int im = 0; im < 4; im++)
                ldsm_x4(a[im], abase + a_rowb[im] + (kb ^ a_rx[im]));
#pragma unroll
            for (int ib = 0; ib < 2; ib++)
                ldsm_x4(bq[ib], bbase + b_rowb[ib] + (kb ^ b_rx[ib]));
#pragma unroll
            for (int im = 0; im < 4; im++) {
#pragma unroll
                for (int ib = 0; ib < 2; ib++) {
                    mma16816(acc[im][2 * ib],     a[im], bq[ib][0], bq[ib][2]);
                    mma16816(acc[im][2 * ib + 1], a[im], bq[ib][1], bq[ib][3]);
                }
            }
        }

        if (lane == 0) {                           // release stage (one per warp)
            asm volatile("mbarrier.arrive.shared.b64 _, [%0];"
                         :: "r"(mb_u + (STAGES + s) * 8) : "memory");
        }
        if (++s == STAGES) { s = 0; phase ^= 1; }
    }

    // --- epilogue: out = fs[m] + cs[n] - cross2 ---
    const int g = lane >> 2;
    const int t = lane & 3;
#pragma unroll
    for (int im = 0; im < 4; im++) {
        int gm = m0 + wm + im * 16 + g;
        float fs0 = g_feat_sq[gm];
        float fs1 = g_feat_sq[gm + 8];
#pragma unroll
        for (int in = 0; in < 4; in++) {
            int gn = n0 + wn + in * 8 + 2 * t;
            float cs0 = g_cent_sq[gn];
            float cs1 = g_cent_sq[gn + 1];
            float2 v0, v1;
            v0.x = fs0 + cs0 - acc[im][in][0];
            v0.y = fs0 + cs1 - acc[im][in][1];
            v1.x = fs1 + cs0 - acc[im][in][2];
            v1.y = fs1 + cs1 - acc[im][in][3];
            *reinterpret_cast<float2*>(out + (size_t)gm * K_ROWS + gn)       = v0;
            *reinterpret_cast<float2*>(out + (size_t)(gm + 8) * K_ROWS + gn) = v1;
        }
    }
}

// ---------------------------------------------------------------------------
extern "C" void kernel_launch(void* const* d_in, const int* in_sizes, int n_in,
                              void* d_out, int out_size) {
    const float* feat = (const float*)d_in[0];
    const float* cent = (const float*)d_in[1];
    float* out = (float*)d_out;

    cudaFuncSetAttribute(dist_gemm_kernel,
                         cudaFuncAttributeMaxDynamicSharedMemorySize, SM_ALLOC);

    convert_norms_kernel<<<(N_ROWS + K_ROWS) / 8, 256>>>(feat, cent);

    dim3 grid(K_ROWS / BN, N_ROWS / BM);
    dist_gemm_kernel<<<grid, NTHREADS, SM_ALLOC>>>(out);
}

// round 8
// speedup vs baseline: 1.5250x; 1.5250x over previous
#include <cuda_runtime.h>
#include <cuda_bf16.h>
#include <cuda_fp8.h>
#include <cstdint>

// ---------------------------------------------------------------------------
// Problem constants
// ---------------------------------------------------------------------------
#define N_ROWS 16384
#define K_ROWS 2048
#define D_DIM  1024

#define BM 128
#define BN 128
#define BK 128                  // fp8 -> 128 B per smem row (SW128 atom)
#define NKT (D_DIM / BK)        // 8 k-tiles
#define STAGES 3
#define A_STAGE_BYTES (BM * 128)                      // 16 KB
#define B_STAGE_BYTES (BN * 128)                      // 16 KB
#define STAGE_BYTES (A_STAGE_BYTES + B_STAGE_BYTES)   // 32 KB
#define SM_ALLOC (STAGES * STAGE_BYTES)               // 96 KB -> 2 CTAs/SM

// fp8 mirrors + squared norms (device globals: allocation-free scratch)
// feat mirror scaled by 2 (exact), cent mirror scaled by 256 (exact):
//   acc = 512 * feat.cent  ->  out = fs + cs - acc * (1/256)   [2*cross folded]
__device__ uint8_t g_feat_f8[(size_t)N_ROWS * D_DIM];   // 16 MB
__device__ uint8_t g_cent_f8[(size_t)K_ROWS * D_DIM];   //  2 MB
__device__ float g_feat_sq[N_ROWS];
__device__ float g_cent_sq[K_ROWS];

// ---------------------------------------------------------------------------
// helpers
// ---------------------------------------------------------------------------
__device__ __forceinline__ void cp_async16(uint32_t saddr, const void* gaddr) {
    asm volatile("cp.async.cg.shared.global [%0], [%1], 16;" :: "r"(saddr), "l"(gaddr));
}

__device__ __forceinline__ void ldsm_x4(uint32_t* r, uint32_t addr) {
    asm volatile("ldmatrix.sync.aligned.m8n8.x4.shared.b16 {%0,%1,%2,%3}, [%4];"
                 : "=r"(r[0]), "=r"(r[1]), "=r"(r[2]), "=r"(r[3]) : "r"(addr));
}

// FP8 e4m3 MMA, K=32 per instruction. Fragment byte-layout == f16 k16 layout.
__device__ __forceinline__ void mma_fp8(float* c, const uint32_t* a,
                                        uint32_t b0, uint32_t b1) {
    asm volatile(
        "mma.sync.aligned.m16n8k32.row.col.f32.e4m3.e4m3.f32 "
        "{%0,%1,%2,%3}, {%4,%5,%6,%7}, {%8,%9}, {%0,%1,%2,%3};\n"
        : "+f"(c[0]), "+f"(c[1]), "+f"(c[2]), "+f"(c[3])
        : "r"(a[0]), "r"(a[1]), "r"(a[2]), "r"(a[3]), "r"(b0), "r"(b1));
}

// ---------------------------------------------------------------------------
// fp32 -> fp8 conversion fused with row squared-norms. One warp per row.
// feat scaled by 2, cent scaled by 256 (both exact powers of two).
// ---------------------------------------------------------------------------
__global__ void convert_norms_kernel(const float* __restrict__ feat,
                                     const float* __restrict__ cent) {
    int grow = blockIdx.x * 8 + (threadIdx.x >> 5);
    int lane = threadIdx.x & 31;
    const float* src;
    uint8_t* dst;
    float* sq;
    int row;
    float scale;
    if (grow < N_ROWS) { src = feat; dst = g_feat_f8; sq = g_feat_sq; row = grow; scale = 2.f; }
    else               { src = cent; dst = g_cent_f8; sq = g_cent_sq; row = grow - N_ROWS; scale = 256.f; }

    const float4* p = reinterpret_cast<const float4*>(src) + (size_t)row * (D_DIM / 4);
    uint32_t* d = reinterpret_cast<uint32_t*>(dst + (size_t)row * D_DIM);
    float s = 0.f;
#pragma unroll
    for (int i = lane; i < D_DIM / 4; i += 32) {
        float4 v = p[i];
        s += v.x * v.x + v.y * v.y + v.z * v.z + v.w * v.w;
        float2 lo = make_float2(v.x * scale, v.y * scale);
        float2 hi = make_float2(v.z * scale, v.w * scale);
        uint16_t plo = __nv_cvt_float2_to_fp8x2(lo, __NV_SATFINITE, __NV_E4M3);
        uint16_t phi = __nv_cvt_float2_to_fp8x2(hi, __NV_SATFINITE, __NV_E4M3);
        d[i] = (uint32_t)plo | ((uint32_t)phi << 16);
    }
#pragma unroll
    for (int o = 16; o > 0; o >>= 1) s += __shfl_xor_sync(0xffffffffu, s, o);
    if (lane == 0) sq[row] = s;
}

// ---------------------------------------------------------------------------
// FP8 distance GEMM: acc = (2*feat) . (256*cent)^T via mma.sync e4m3.
// 3-stage cp.async pipeline, SW128 swizzle, ldmatrix x4 fragment loads.
// 256 threads = 8 warps (2 M x 4 N), warp tile 64 x 32, 2 CTAs/SM.
// out = feat_sq[m] + cent_sq[n] - acc/256
// ---------------------------------------------------------------------------
__global__ void __launch_bounds__(256, 2)
dist_gemm_kernel(float* __restrict__ out) {
    extern __shared__ __align__(1024) char smem[];
    const uint32_t smem_u = (uint32_t)__cvta_generic_to_shared(smem);

    const int tid  = threadIdx.x;
    const int warp = tid >> 5;
    const int lane = tid & 31;

    const int wm = (warp >> 2) * 64;   // warp M offset: 0 / 64
    const int wn = (warp & 3) * 32;    // warp N offset: 0 / 32 / 64 / 96

    const int m0 = blockIdx.y * BM;
    const int n0 = blockIdx.x * BN;

    // cp.async slot mapping: 1024 16B chunks per tile, 4 per thread
    const int ld_row = tid >> 1;            // 0..127 (2 threads per row)
    const int ld_q0  = (tid & 1) * 4;       // chunk 0..3 or 4..7

    const uint8_t* agbase = g_feat_f8 + (size_t)(m0 + ld_row) * D_DIM + ld_q0 * 16;
    const uint8_t* bgbase = g_cent_f8 + (size_t)(n0 + ld_row) * D_DIM + ld_q0 * 16;
    const uint32_t ld_sw_row = ld_row * 128;
    const uint32_t ld_rx     = (ld_row & 7) << 4;

    auto load_stage = [&](int s, int kt) {
        const uint32_t abase = smem_u + s * STAGE_BYTES;
        const uint32_t bbase = abase + A_STAGE_BYTES;
        const uint8_t* ag = agbase + kt * BK;
        const uint8_t* bg = bgbase + kt * BK;
#pragma unroll
        for (int j = 0; j < 4; j++) {
            uint32_t so = ld_sw_row + ((((ld_q0 + j) * 16) ^ ld_rx));
            cp_async16(abase + so, ag + j * 16);
            cp_async16(bbase + so, bg + j * 16);
        }
    };

    // ldmatrix lane addressing (constant parts); fp8 k32 fragments are
    // byte-identical to bf16 k16 fragments -> same addressing with 32B k-chunks.
    const int fr_lo = lane & 15;                 // row within 16-row fragment
    const uint32_t fr_hi16 = (lane >> 4) * 16;   // k-byte offset 0/16

    uint32_t a_rowb[4], a_rx[4], b_rowb[2], b_rx[2];
#pragma unroll
    for (int im = 0; im < 4; im++) {
        int r = wm + im * 16 + fr_lo;
        a_rowb[im] = r * 128;
        a_rx[im]   = (r & 7) << 4;
    }
#pragma unroll
    for (int ib = 0; ib < 2; ib++) {
        int r = wn + ib * 16 + fr_lo;
        b_rowb[ib] = r * 128;
        b_rx[ib]   = (r & 7) << 4;
    }

    float acc[4][4][4] = {};   // [im][in][creg]

    // --- prologue: fill STAGES-1 stages ---
#pragma unroll
    for (int s = 0; s < STAGES - 1; s++) {
        load_stage(s, s);
        asm volatile("cp.async.commit_group;" ::: "memory");
    }

    for (int kt = 0; kt < NKT; kt++) {
        asm volatile("cp.async.wait_group %0;" :: "n"(STAGES - 2) : "memory");
        __syncthreads();

        if (kt + STAGES - 1 < NKT)
            load_stage((kt + STAGES - 1) % STAGES, kt + STAGES - 1);
        asm volatile("cp.async.commit_group;" ::: "memory");

        const uint32_t abase = smem_u + (kt % STAGES) * STAGE_BYTES;
        const uint32_t bbase = abase + A_STAGE_BYTES;

#pragma unroll
        for (int ks = 0; ks < 4; ks++) {       // 4 x K=32 fp8 per 128B row
            const uint32_t kb = ks * 32 + fr_hi16;
            uint32_t a[4][4], bq[2][4];
#pragma unroll
            for (int im = 0; im < 4; im++)
                ldsm_x4(a[im], abase + a_rowb[im] + (kb ^ a_rx[im]));
#pragma unroll
            for (int ib = 0; ib < 2; ib++)
                ldsm_x4(bq[ib], bbase + b_rowb[ib] + (kb ^ b_rx[ib]));
#pragma unroll
            for (int im = 0; im < 4; im++) {
#pragma unroll
                for (int ib = 0; ib < 2; ib++) {
                    mma_fp8(acc[im][2 * ib],     a[im], bq[ib][0], bq[ib][2]);
                    mma_fp8(acc[im][2 * ib + 1], a[im], bq[ib][1], bq[ib][3]);
                }
            }
        }
    }

    // --- epilogue: out = fs[m] + cs[n] - acc/256 ---
    const float inv = 1.0f / 256.0f;           // exact
    const int g = lane >> 2;
    const int t = lane & 3;
#pragma unroll
    for (int im = 0; im < 4; im++) {
        int gm = m0 + wm + im * 16 + g;
        float fs0 = g_feat_sq[gm];
        float fs1 = g_feat_sq[gm + 8];
#pragma unroll
        for (int in = 0; in < 4; in++) {
            int gn = n0 + wn + in * 8 + 2 * t;
            float cs0 = g_cent_sq[gn];
            float cs1 = g_cent_sq[gn + 1];
            float2 v0, v1;
            v0.x = fs0 + cs0 - acc[im][in][0] * inv;
            v0.y = fs0 + cs1 - acc[im][in][1] * inv;
            v1.x = fs1 + cs0 - acc[im][in][2] * inv;
            v1.y = fs1 + cs1 - acc[im][in][3] * inv;
            *reinterpret_cast<float2*>(out + (size_t)gm * K_ROWS + gn)       = v0;
            *reinterpret_cast<float2*>(out + (size_t)(gm + 8) * K_ROWS + gn) = v1;
        }
    }
}

// ---------------------------------------------------------------------------
extern "C" void kernel_launch(void* const* d_in, const int* in_sizes, int n_in,
                              void* d_out, int out_size) {
    const float* feat = (const float*)d_in[0];
    const float* cent = (const float*)d_in[1];
    float* out = (float*)d_out;

    cudaFuncSetAttribute(dist_gemm_kernel,
                         cudaFuncAttributeMaxDynamicSharedMemorySize, SM_ALLOC);

    convert_norms_kernel<<<(N_ROWS + K_ROWS) / 8, 256>>>(feat, cent);

    dim3 grid(K_ROWS / BN, N_ROWS / BM);
    dist_gemm_kernel<<<grid, 256, SM_ALLOC>>>(out);
}

// round 9
// speedup vs baseline: 1.7225x; 1.1295x over previous
#include <cuda_runtime.h>
#include <cuda_bf16.h>
#include <cuda_fp8.h>
#include <cstdint>

// ---------------------------------------------------------------------------
// Problem constants
// ---------------------------------------------------------------------------
#define N_ROWS 16384
#define K_ROWS 2048
#define D_DIM  1024

#define BM 128
#define BN 128
#define BK 128                  // fp8 -> 128 B per smem row (SW128 atom)
#define NKT (D_DIM / BK)        // 8 k-tiles
#define STAGES 3
#define A_STAGE_BYTES (BM * 128)                      // 16 KB
#define B_STAGE_BYTES (BN * 128)                      // 16 KB
#define STAGE_BYTES (A_STAGE_BYTES + B_STAGE_BYTES)   // 32 KB
#define SM_ALLOC (STAGES * STAGE_BYTES)               // 96 KB -> 2 CTAs/SM

// fp8 mirrors + squared norms (device globals: allocation-free scratch)
// feat mirror scaled by 2 (exact), cent mirror scaled by 256 (exact):
//   acc = 512 * feat.cent  ->  out = fs + cs - acc * (1/256)
__device__ uint8_t g_feat_f8[(size_t)N_ROWS * D_DIM];   // 16 MB
__device__ uint8_t g_cent_f8[(size_t)K_ROWS * D_DIM];   //  2 MB
__device__ float g_feat_sq[N_ROWS];
__device__ float g_cent_sq[K_ROWS];

// ---------------------------------------------------------------------------
// helpers
// ---------------------------------------------------------------------------
__device__ __forceinline__ void cp_async16(uint32_t saddr, const void* gaddr) {
    asm volatile("cp.async.cg.shared.global [%0], [%1], 16;" :: "r"(saddr), "l"(gaddr));
}

__device__ __forceinline__ void ldsm_x4(uint32_t* r, uint32_t addr) {
    asm volatile("ldmatrix.sync.aligned.m8n8.x4.shared.b16 {%0,%1,%2,%3}, [%4];"
                 : "=r"(r[0]), "=r"(r[1]), "=r"(r[2]), "=r"(r[3]) : "r"(addr));
}

// FP8 e4m3 MMA, K=32. Fragment byte-layout == f16 k16 layout.
__device__ __forceinline__ void mma_fp8(float* c, const uint32_t* a,
                                        uint32_t b0, uint32_t b1) {
    asm volatile(
        "mma.sync.aligned.m16n8k32.row.col.f32.e4m3.e4m3.f32 "
        "{%0,%1,%2,%3}, {%4,%5,%6,%7}, {%8,%9}, {%0,%1,%2,%3};\n"
        : "+f"(c[0]), "+f"(c[1]), "+f"(c[2]), "+f"(c[3])
        : "r"(a[0]), "r"(a[1]), "r"(a[2]), "r"(a[3]), "r"(b0), "r"(b1));
}

// acquire-parity wait (try_wait fast path + poll loop).
__device__ __forceinline__ void mbar_wait(uint32_t mbar, uint32_t parity) {
    uint32_t done;
    asm volatile(
        "{\n\t.reg .pred p;\n\t"
        "mbarrier.try_wait.parity.acquire.cta.shared::cta.b64 p, [%1], %2;\n\t"
        "selp.b32 %0, 1, 0, p;\n\t}"
        : "=r"(done) : "r"(mbar), "r"(parity) : "memory");
    if (!done) {
        asm volatile(
            "{\n\t.reg .pred P1;\n\t"
            "WL_%=:\n\t"
            "mbarrier.try_wait.parity.acquire.cta.shared::cta.b64 P1, [%0], %1, 0x989680;\n\t"
            "@P1 bra.uni WD_%=;\n\t"
            "bra.uni WL_%=;\n\t"
            "WD_%=:\n\t}"
            :: "r"(mbar), "r"(parity) : "memory");
    }
}

// ---------------------------------------------------------------------------
// fp32 -> fp8 conversion fused with row squared-norms. One warp per row.
// feat scaled by 2, cent scaled by 256 (both exact powers of two).
// ---------------------------------------------------------------------------
__global__ void convert_norms_kernel(const float* __restrict__ feat,
                                     const float* __restrict__ cent) {
    int grow = blockIdx.x * 8 + (threadIdx.x >> 5);
    int lane = threadIdx.x & 31;
    const float* src;
    uint8_t* dst;
    float* sq;
    int row;
    float scale;
    if (grow < N_ROWS) { src = feat; dst = g_feat_f8; sq = g_feat_sq; row = grow; scale = 2.f; }
    else               { src = cent; dst = g_cent_f8; sq = g_cent_sq; row = grow - N_ROWS; scale = 256.f; }

    const float4* p = reinterpret_cast<const float4*>(src) + (size_t)row * (D_DIM / 4);
    uint32_t* d = reinterpret_cast<uint32_t*>(dst + (size_t)row * D_DIM);
    float s = 0.f;
#pragma unroll
    for (int i = lane; i < D_DIM / 4; i += 32) {
        float4 v = p[i];
        s += v.x * v.x + v.y * v.y + v.z * v.z + v.w * v.w;
        float2 lo = make_float2(v.x * scale, v.y * scale);
        float2 hi = make_float2(v.z * scale, v.w * scale);
        uint16_t plo = __nv_cvt_float2_to_fp8x2(lo, __NV_SATFINITE, __NV_E4M3);
        uint16_t phi = __nv_cvt_float2_to_fp8x2(hi, __NV_SATFINITE, __NV_E4M3);
        d[i] = (uint32_t)plo | ((uint32_t)phi << 16);
    }
#pragma unroll
    for (int o = 16; o > 0; o >>= 1) s += __shfl_xor_sync(0xffffffffu, s, o);
    if (lane == 0) sq[row] = s;
}

// ---------------------------------------------------------------------------
// FP8 distance GEMM, free-running warps (no mainloop __syncthreads).
//   all 8 warps produce (cp.async + arrive.noinc on full[s], count 256)
//   and consume (wait full -> LDSM+MMA -> lane0 arrive empty[s], count 8).
// Stage ring of 3 absorbs up to 2 k-tiles of inter-warp skew.
// out = feat_sq[m] + cent_sq[n] - acc/256
// ---------------------------------------------------------------------------
__global__ void __launch_bounds__(256, 2)
dist_gemm_kernel(float* __restrict__ out) {
    extern __shared__ __align__(1024) char smem[];
    __shared__ __align__(8) uint64_t mbars[2 * STAGES];   // [full0..2, empty0..2]
    const uint32_t smem_u = (uint32_t)__cvta_generic_to_shared(smem);
    const uint32_t mb_u   = (uint32_t)__cvta_generic_to_shared(mbars);

    const int tid  = threadIdx.x;
    const int warp = tid >> 5;
    const int lane = tid & 31;

    const int wm = (warp >> 2) * 64;   // warp M offset: 0 / 64
    const int wn = (warp & 3) * 32;    // warp N offset: 0 / 32 / 64 / 96

    const int m0 = blockIdx.y * BM;
    const int n0 = blockIdx.x * BN;

    if (tid == 0) {
#pragma unroll
        for (int s = 0; s < STAGES; s++) {
            asm volatile("mbarrier.init.shared.b64 [%0], 256;"
                         :: "r"(mb_u + s * 8) : "memory");                 // full
            asm volatile("mbarrier.init.shared.b64 [%0], 8;"
                         :: "r"(mb_u + (STAGES + s) * 8) : "memory");      // empty
        }
    }
    __syncthreads();

    // --- producer addressing: 8 x 16B chunks per thread per stage ---
    const int ld_row = tid >> 1;            // 0..127 (2 threads per row)
    const int ld_q0  = (tid & 1) * 4;       // chunk 0..3 or 4..7
    const uint8_t* agbase = g_feat_f8 + (size_t)(m0 + ld_row) * D_DIM + ld_q0 * 16;
    const uint8_t* bgbase = g_cent_f8 + (size_t)(n0 + ld_row) * D_DIM + ld_q0 * 16;
    const uint32_t ld_sw_row = ld_row * 128;
    const uint32_t ld_rx     = (ld_row & 7) << 4;

    // produce k-tile kt into stage s; arrive.noinc on full[s] when landed
    auto produce = [&](int s, int kt) {
        const uint32_t abase = smem_u + s * STAGE_BYTES;
        const uint32_t bbase = abase + A_STAGE_BYTES;
        const uint8_t* ag = agbase + kt * BK;
        const uint8_t* bg = bgbase + kt * BK;
#pragma unroll
        for (int j = 0; j < 4; j++) {
            uint32_t so = ld_sw_row + ((((ld_q0 + j) * 16) ^ ld_rx));
            cp_async16(abase + so, ag + j * 16);
            cp_async16(bbase + so, bg + j * 16);
        }
        asm volatile("cp.async.mbarrier.arrive.noinc.shared::cta.b64 [%0];"
                     :: "r"(mb_u + s * 8) : "memory");
    };

    // --- consumer addressing (constant parts) ---
    const int fr_lo = lane & 15;
    const uint32_t fr_hi16 = (lane >> 4) * 16;

    uint32_t a_rowb[4], a_rx[4], b_rowb[2], b_rx[2];
#pragma unroll
    for (int im = 0; im < 4; im++) {
        int r = wm + im * 16 + fr_lo;
        a_rowb[im] = r * 128;
        a_rx[im]   = (r & 7) << 4;
    }
#pragma unroll
    for (int ib = 0; ib < 2; ib++) {
        int r = wn + ib * 16 + fr_lo;
        b_rowb[ib] = r * 128;
        b_rx[ib]   = (r & 7) << 4;
    }

    float acc[4][4][4] = {};   // [im][in][creg]

    // --- cursors ---
    int ps = 0, pph = 1;       // producer: wait empty[ps] at parity pph
    int cs = 0, cph = 0;       // consumer: wait full[cs] at parity cph

    // prologue: fill 2 stages (fresh empty barriers -> parity-1 wait passes)
#pragma unroll
    for (int k = 0; k < STAGES - 1; k++) {
        mbar_wait(mb_u + (STAGES + ps) * 8, (uint32_t)pph);
        produce(ps, k);
        if (++ps == STAGES) { ps = 0; pph ^= 1; }
    }

    for (int kt = 0; kt < NKT; kt++) {
        mbar_wait(mb_u + cs * 8, (uint32_t)cph);     // wait stage full
        const uint32_t abase = smem_u + cs * STAGE_BYTES;
        const uint32_t bbase = abase + A_STAGE_BYTES;

#pragma unroll
        for (int ks = 0; ks < 4; ks++) {             // 4 x K=32 fp8 per 128B row
            const uint32_t kb = ks * 32 + fr_hi16;
            uint32_t a[4][4], bq[2][4];
#pragma unroll
            for (int im = 0; im < 4; im++)
                ldsm_x4(a[im], abase + a_rowb[im] + (kb ^ a_rx[im]));
#pragma unroll
            for (int ib = 0; ib < 2; ib++)
                ldsm_x4(bq[ib], bbase + b_rowb[ib] + (kb ^ b_rx[ib]));
#pragma unroll
            for (int im = 0; im < 4; im++) {
#pragma unroll
                for (int ib = 0; ib < 2; ib++) {
                    mma_fp8(acc[im][2 * ib],     a[im], bq[ib][0], bq[ib][2]);
                    mma_fp8(acc[im][2 * ib + 1], a[im], bq[ib][1], bq[ib][3]);
                }
            }
        }

        if (lane == 0) {                             // release stage
            asm volatile("mbarrier.arrive.shared.b64 _, [%0];"
                         :: "r"(mb_u + (STAGES + cs) * 8) : "memory");
        }
        if (++cs == STAGES) { cs = 0; cph ^= 1; }

        if (kt + STAGES - 1 < NKT) {                 // refill (stage freed at kt-1)
            mbar_wait(mb_u + (STAGES + ps) * 8, (uint32_t)pph);
            produce(ps, kt + STAGES - 1);
            if (++ps == STAGES) { ps = 0; pph ^= 1; }
        }
    }

    // --- epilogue: out = fs[m] + cs[n] - acc/256 ---
    const float inv = 1.0f / 256.0f;                 // exact
    const int g = lane >> 2;
    const int t = lane & 3;
#pragma unroll
    for (int im = 0; im < 4; im++) {
        int gm = m0 + wm + im * 16 + g;
        float fs0 = g_feat_sq[gm];
        float fs1 = g_feat_sq[gm + 8];
#pragma unroll
        for (int in = 0; in < 4; in++) {
            int gn = n0 + wn + in * 8 + 2 * t;
            float cs0 = g_cent_sq[gn];
            float cs1 = g_cent_sq[gn + 1];
            float2 v0, v1;
            v0.x = fs0 + cs0 - acc[im][in][0] * inv;
            v0.y = fs0 + cs1 - acc[im][in][1] * inv;
            v1.x = fs1 + cs0 - acc[im][in][2] * inv;
            v1.y = fs1 + cs1 - acc[im][in][3] * inv;
            *reinterpret_cast<float2*>(out + (size_t)gm * K_ROWS + gn)       = v0;
            *reinterpret_cast<float2*>(out + (size_t)(gm + 8) * K_ROWS + gn) = v1;
        }
    }
}

// ---------------------------------------------------------------------------
extern "C" void kernel_launch(void* const* d_in, const int* in_sizes, int n_in,
                              void* d_out, int out_size) {
    const float* feat = (const float*)d_in[0];
    const float* cent = (const float*)d_in[1];
    float* out = (float*)d_out;

    cudaFuncSetAttribute(dist_gemm_kernel,
                         cudaFuncAttributeMaxDynamicSharedMemorySize, SM_ALLOC);

    convert_norms_kernel<<<(N_ROWS + K_ROWS) / 8, 256>>>(feat, cent);

    dim3 grid(K_ROWS / BN, N_ROWS / BM);
    dist_gemm_kernel<<<grid, 256, SM_ALLOC>>>(out);
}

// round 10
// speedup vs baseline: 1.7269x; 1.0025x over previous
#include <cuda_runtime.h>
#include <cuda_bf16.h>
#include <cuda_fp8.h>
#include <cstdint>

// ---------------------------------------------------------------------------
// Problem constants
// ---------------------------------------------------------------------------
#define N_ROWS 16384
#define K_ROWS 2048
#define D_DIM  1024

#define BM 128
#define BN 128
#define BK 128                  // fp8 -> 128 B per smem row (SW128 atom)
#define KT_PER_TILE 8           // D / BK
#define NTILES 2048             // (N/BM) * (K/BN) = 128 * 16
#define TN 16                   // tiles along n
#define GRID_P 296              // persistent CTAs (~2 per SM)
#define STAGES 3
#define A_STAGE_BYTES (BM * 128)                      // 16 KB
#define B_STAGE_BYTES (BN * 128)                      // 16 KB
#define STAGE_BYTES (A_STAGE_BYTES + B_STAGE_BYTES)   // 32 KB
#define SM_ALLOC (STAGES * STAGE_BYTES)               // 96 KB -> 2 CTAs/SM

// fp8 mirrors + squared norms (device globals: allocation-free scratch)
// feat scaled by 2 (exact), cent scaled by 256 (exact):
//   acc = 512*feat.cent -> out = fs + cs - acc/256
__device__ uint8_t g_feat_f8[(size_t)N_ROWS * D_DIM];   // 16 MB
__device__ uint8_t g_cent_f8[(size_t)K_ROWS * D_DIM];   //  2 MB
__device__ float g_feat_sq[N_ROWS];
__device__ float g_cent_sq[K_ROWS];

// ---------------------------------------------------------------------------
// helpers
// ---------------------------------------------------------------------------
__device__ __forceinline__ void cp_async16(uint32_t saddr, const void* gaddr) {
    asm volatile("cp.async.cg.shared.global [%0], [%1], 16;" :: "r"(saddr), "l"(gaddr));
}

__device__ __forceinline__ void ldsm_x4(uint32_t* r, uint32_t addr) {
    asm volatile("ldmatrix.sync.aligned.m8n8.x4.shared.b16 {%0,%1,%2,%3}, [%4];"
                 : "=r"(r[0]), "=r"(r[1]), "=r"(r[2]), "=r"(r[3]) : "r"(addr));
}

__device__ __forceinline__ void mma_fp8(float* c, const uint32_t* a,
                                        uint32_t b0, uint32_t b1) {
    asm volatile(
        "mma.sync.aligned.m16n8k32.row.col.f32.e4m3.e4m3.f32 "
        "{%0,%1,%2,%3}, {%4,%5,%6,%7}, {%8,%9}, {%0,%1,%2,%3};\n"
        : "+f"(c[0]), "+f"(c[1]), "+f"(c[2]), "+f"(c[3])
        : "r"(a[0]), "r"(a[1]), "r"(a[2]), "r"(a[3]), "r"(b0), "r"(b1));
}

__device__ __forceinline__ void mbar_wait(uint32_t mbar, uint32_t parity) {
    uint32_t done;
    asm volatile(
        "{\n\t.reg .pred p;\n\t"
        "mbarrier.try_wait.parity.acquire.cta.shared::cta.b64 p, [%1], %2;\n\t"
        "selp.b32 %0, 1, 0, p;\n\t}"
        : "=r"(done) : "r"(mbar), "r"(parity) : "memory");
    if (!done) {
        asm volatile(
            "{\n\t.reg .pred P1;\n\t"
            "WL_%=:\n\t"
            "mbarrier.try_wait.parity.acquire.cta.shared::cta.b64 P1, [%0], %1, 0x989680;\n\t"
            "@P1 bra.uni WD_%=;\n\t"
            "bra.uni WL_%=;\n\t"
            "WD_%=:\n\t}"
            :: "r"(mbar), "r"(parity) : "memory");
    }
}

// ---------------------------------------------------------------------------
// fp32 -> fp8 conversion fused with row squared-norms. One warp per row.
// ---------------------------------------------------------------------------
__global__ void convert_norms_kernel(const float* __restrict__ feat,
                                     const float* __restrict__ cent) {
    int grow = blockIdx.x * 8 + (threadIdx.x >> 5);
    int lane = threadIdx.x & 31;
    const float* src;
    uint8_t* dst;
    float* sq;
    int row;
    float scale;
    if (grow < N_ROWS) { src = feat; dst = g_feat_f8; sq = g_feat_sq; row = grow; scale = 2.f; }
    else               { src = cent; dst = g_cent_f8; sq = g_cent_sq; row = grow - N_ROWS; scale = 256.f; }

    const float4* p = reinterpret_cast<const float4*>(src) + (size_t)row * (D_DIM / 4);
    uint32_t* d = reinterpret_cast<uint32_t*>(dst + (size_t)row * D_DIM);
    float s = 0.f;
#pragma unroll
    for (int i = lane; i < D_DIM / 4; i += 32) {
        float4 v = p[i];
        s += v.x * v.x + v.y * v.y + v.z * v.z + v.w * v.w;
        float2 lo = make_float2(v.x * scale, v.y * scale);
        float2 hi = make_float2(v.z * scale, v.w * scale);
        uint16_t plo = __nv_cvt_float2_to_fp8x2(lo, __NV_SATFINITE, __NV_E4M3);
        uint16_t phi = __nv_cvt_float2_to_fp8x2(hi, __NV_SATFINITE, __NV_E4M3);
        d[i] = (uint32_t)plo | ((uint32_t)phi << 16);
    }
#pragma unroll
    for (int o = 16; o > 0; o >>= 1) s += __shfl_xor_sync(0xffffffffu, s, o);
    if (lane == 0) sq[row] = s;
}

// ---------------------------------------------------------------------------
// Persistent FP8 distance GEMM. Each CTA walks tiles t = bid, bid+GRID_P, ...
// with ONE continuous produce/consume step stream across all its tiles:
// the stage ring never drains at tile boundaries (next tile's loads are in
// flight during the epilogue). Free-running warps, R8 mbarrier protocol.
// ---------------------------------------------------------------------------
__global__ void __launch_bounds__(256, 2)
dist_gemm_kernel(float* __restrict__ out) {
    extern __shared__ __align__(1024) char smem[];
    __shared__ __align__(8) uint64_t mbars[2 * STAGES];   // [full0..2, empty0..2]
    const uint32_t smem_u = (uint32_t)__cvta_generic_to_shared(smem);
    const uint32_t mb_u   = (uint32_t)__cvta_generic_to_shared(mbars);

    const int tid  = threadIdx.x;
    const int warp = tid >> 5;
    const int lane = tid & 31;
    const int bid  = blockIdx.x;

    const int wm = (warp >> 2) * 64;
    const int wn = (warp & 3) * 32;

    if (tid == 0) {
#pragma unroll
        for (int s = 0; s < STAGES; s++) {
            asm volatile("mbarrier.init.shared.b64 [%0], 256;"
                         :: "r"(mb_u + s * 8) : "memory");                 // full
            asm volatile("mbarrier.init.shared.b64 [%0], 8;"
                         :: "r"(mb_u + (STAGES + s) * 8) : "memory");      // empty
        }
    }
    __syncthreads();

    // --- producer addressing (row/chunk constants) ---
    const int ld_row = tid >> 1;
    const int ld_q0  = (tid & 1) * 4;
    const uint32_t ld_sw_row = ld_row * 128;
    const uint32_t ld_rx     = (ld_row & 7) << 4;

    // produce global step st into stage s (tile = st/8, kt = st%8)
    auto produce = [&](int s, int st) {
        const int t  = bid + (st >> 3) * GRID_P;
        const int kt = st & 7;
        const int m0 = (t >> 4) << 7;        // (t / TN) * BM
        const int n0 = (t & (TN - 1)) << 7;  // (t % TN) * BN
        const uint32_t abase = smem_u + s * STAGE_BYTES;
        const uint32_t bbase = abase + A_STAGE_BYTES;
        const uint8_t* ag = g_feat_f8 + (size_t)(m0 + ld_row) * D_DIM + kt * BK + ld_q0 * 16;
        const uint8_t* bg = g_cent_f8 + (size_t)(n0 + ld_row) * D_DIM + kt * BK + ld_q0 * 16;
#pragma unroll
        for (int j = 0; j < 4; j++) {
            uint32_t so = ld_sw_row + ((((ld_q0 + j) * 16) ^ ld_rx));
            cp_async16(abase + so, ag + j * 16);
            cp_async16(bbase + so, bg + j * 16);
        }
        asm volatile("cp.async.mbarrier.arrive.noinc.shared::cta.b64 [%0];"
                     :: "r"(mb_u + s * 8) : "memory");
    };

    // --- consumer addressing (constant parts) ---
    const int fr_lo = lane & 15;
    const uint32_t fr_hi16 = (lane >> 4) * 16;

    uint32_t a_rowb[4], a_rx[4], b_rowb[2], b_rx[2];
#pragma unroll
    for (int im = 0; im < 4; im++) {
        int r = wm + im * 16 + fr_lo;
        a_rowb[im] = r * 128;
        a_rx[im]   = (r & 7) << 4;
    }
#pragma unroll
    for (int ib = 0; ib < 2; ib++) {
        int r = wn + ib * 16 + fr_lo;
        b_rowb[ib] = r * 128;
        b_rx[ib]   = (r & 7) << 4;
    }

    float acc[4][4][4] = {};

    const int ntiles = (NTILES - bid + GRID_P - 1) / GRID_P;
    const int nsteps = ntiles * KT_PER_TILE;

    int ps = 0, pph = 1;       // producer cursor
    int cs = 0, cph = 0;       // consumer cursor

    // prologue: fill 2 stages (fresh empty barriers pass at parity 1)
#pragma unroll
    for (int k = 0; k < STAGES - 1; k++) {
        mbar_wait(mb_u + (STAGES + ps) * 8, (uint32_t)pph);
        produce(ps, k);
        if (++ps == STAGES) { ps = 0; pph ^= 1; }
    }

    for (int st = 0; st < nsteps; st++) {
        mbar_wait(mb_u + cs * 8, (uint32_t)cph);
        const uint32_t abase = smem_u + cs * STAGE_BYTES;
        const uint32_t bbase = abase + A_STAGE_BYTES;

#pragma unroll
        for (int ks = 0; ks < 4; ks++) {
            // rotate ks per warp: staggers the post-wake LDSM bursts so the
            // smem crossbar overlaps other warps' MMA issue
            const int kse = (ks + warp) & 3;
            const uint32_t kb = kse * 32 + fr_hi16;
            uint32_t a[4][4], bq[2][4];
#pragma unroll
            for (int im = 0; im < 4; im++)
                ldsm_x4(a[im], abase + a_rowb[im] + (kb ^ a_rx[im]));
#pragma unroll
            for (int ib = 0; ib < 2; ib++)
                ldsm_x4(bq[ib], bbase + b_rowb[ib] + (kb ^ b_rx[ib]));
#pragma unroll
            for (int im = 0; im < 4; im++) {
#pragma unroll
                for (int ib = 0; ib < 2; ib++) {
                    mma_fp8(acc[im][2 * ib],     a[im], bq[ib][0], bq[ib][2]);
                    mma_fp8(acc[im][2 * ib + 1], a[im], bq[ib][1], bq[ib][3]);
                }
            }
        }

        if (lane == 0) {
            asm volatile("mbarrier.arrive.shared.b64 _, [%0];"
                         :: "r"(mb_u + (STAGES + cs) * 8) : "memory");
        }
        if (++cs == STAGES) { cs = 0; cph ^= 1; }

        if (st + STAGES - 1 < nsteps) {          // keep ring full across tiles
            mbar_wait(mb_u + (STAGES + ps) * 8, (uint32_t)pph);
            produce(ps, st + STAGES - 1);
            if (++ps == STAGES) { ps = 0; pph ^= 1; }
        }

        if ((st & 7) == 7) {
            // ---- epilogue for finished tile; ring stays warm meanwhile ----
            const int t  = bid + (st >> 3) * GRID_P;
            const int m0 = (t >> 4) << 7;
            const int n0 = (t & (TN - 1)) << 7;
            const float inv = 1.0f / 256.0f;
            const int g = lane >> 2;
            const int tt = lane & 3;
#pragma unroll
            for (int im = 0; im < 4; im++) {
                int gm = m0 + wm + im * 16 + g;
                float fs0 = g_feat_sq[gm];
                float fs1 = g_feat_sq[gm + 8];
#pragma unroll
                for (int in = 0; in < 4; in++) {
                    int gn = n0 + wn + in * 8 + 2 * tt;
                    float cs0 = g_cent_sq[gn];
                    float cs1 = g_cent_sq[gn + 1];
                    float2 v0, v1;
                    v0.x = fs0 + cs0 - acc[im][in][0] * inv;
                    v0.y = fs0 + cs1 - acc[im][in][1] * inv;
                    v1.x = fs1 + cs0 - acc[im][in][2] * inv;
                    v1.y = fs1 + cs1 - acc[im][in][3] * inv;
                    *reinterpret_cast<float2*>(out + (size_t)gm * K_ROWS + gn)       = v0;
                    *reinterpret_cast<float2*>(out + (size_t)(gm + 8) * K_ROWS + gn) = v1;
                }
            }
#pragma unroll
            for (int im = 0; im < 4; im++)
#pragma unroll
                for (int in = 0; in < 4; in++)
#pragma unroll
                    for (int c = 0; c < 4; c++)
                        acc[im][in][c] = 0.f;
        }
    }
}

// ---------------------------------------------------------------------------
extern "C" void kernel_launch(void* const* d_in, const int* in_sizes, int n_in,
                              void* d_out, int out_size) {
    const float* feat = (const float*)d_in[0];
    const float* cent = (const float*)d_in[1];
    float* out = (float*)d_out;

    cudaFuncSetAttribute(dist_gemm_kernel,
                         cudaFuncAttributeMaxDynamicSharedMemorySize, SM_ALLOC);

    convert_norms_kernel<<<(N_ROWS + K_ROWS) / 8, 256>>>(feat, cent);

    dist_gemm_kernel<<<GRID_P, 256, SM_ALLOC>>>(out);
}